// round 15
// baseline (speedup 1.0000x reference)
#include <cuda_runtime.h>
#include <cuda_bf16.h>
#include <cuda_fp16.h>
#include <cstdint>
#include <string.h>

// ---------------- problem constants ----------------
#define KB    2
#define KNV   6
#define KM    1369
#define KDIM  384
#define KV    65536
#define KPF   64
#define KHID  256
#define KOUT  16
#define KGRID 37
#define KGV   (KB*KV)
#define ROWS_T (KB*KM)        // 2738
#define ROWS_PAD 2752         // 43*64

// ---------------- device scratch ----------------
__device__ __half g_T16[ROWS_T*KHID];      // token table fp16 (incl b1)
__device__ unsigned char g_B1[32768];      // W1top^T fp16, swizzled [256r][128B]
__device__ unsigned char g_B2[8192];       // W2^T    fp16, swizzled [16r][512B]
// W1bot^T bf16, 6 chunks of k64: chunk c: hi plane [256r][128B] then lo plane
__device__ unsigned char g_TB[6*2*32768];

// ---------------- helpers ----------------
__device__ __forceinline__ uint32_t smem_u32(const void* p) {
    uint32_t a;
    asm("{ .reg .u64 t; cvta.to.shared.u64 t, %1; cvt.u32.u64 %0, t; }" : "=r"(a) : "l"(p));
    return a;
}
__device__ __forceinline__ void ldsm4(uint32_t a, uint32_t* r) {
    asm volatile("ldmatrix.sync.aligned.m8n8.x4.shared.b16 {%0,%1,%2,%3}, [%4];"
        : "=r"(r[0]), "=r"(r[1]), "=r"(r[2]), "=r"(r[3]) : "r"(a));
}
// bf16 mma (table kernel)
__device__ __forceinline__ void mma16816(float* c, const uint32_t* a, const uint32_t* b) {
    asm volatile("mma.sync.aligned.m16n8k16.row.col.f32.bf16.bf16.f32 "
        "{%0,%1,%2,%3}, {%4,%5,%6,%7}, {%8,%9}, {%0,%1,%2,%3};"
        : "+f"(c[0]), "+f"(c[1]), "+f"(c[2]), "+f"(c[3])
        : "r"(a[0]), "r"(a[1]), "r"(a[2]), "r"(a[3]), "r"(b[0]), "r"(b[1]));
}
// fp16 mma (fused kernel)
__device__ __forceinline__ void mma16816h(float* c, const uint32_t* a, const uint32_t* b) {
    asm volatile("mma.sync.aligned.m16n8k16.row.col.f32.f16.f16.f32 "
        "{%0,%1,%2,%3}, {%4,%5,%6,%7}, {%8,%9}, {%0,%1,%2,%3};"
        : "+f"(c[0]), "+f"(c[1]), "+f"(c[2]), "+f"(c[3])
        : "r"(a[0]), "r"(a[1]), "r"(a[2]), "r"(a[3]), "r"(b[0]), "r"(b[1]));
}
#define MBAR_INIT(a, n) asm volatile("mbarrier.init.shared.b64 [%0], %1;" :: "r"(a), "r"(n) : "memory")
#define MBAR_EXPECT(a, b) asm volatile("mbarrier.arrive.expect_tx.shared.b64 _, [%0], %1;" :: "r"(a), "r"(b) : "memory")
#define MBAR_WAIT(a, ph) do { \
    uint32_t _m = (a), _p = (ph), _d; \
    asm volatile("{ .reg .pred p; mbarrier.try_wait.parity.shared.b64 p, [%1], %2; selp.b32 %0,1,0,p; }" \
        : "=r"(_d) : "r"(_m), "r"(_p) : "memory"); \
    if (!_d) { \
        asm volatile("{ .reg .pred P1;\nWL_%=:\n mbarrier.try_wait.parity.shared.b64 P1, [%0], %1;\n @P1 bra.uni WD_%=;\n bra.uni WL_%=;\nWD_%=:\n}" \
            :: "r"(_m), "r"(_p) : "memory"); \
    } } while (0)
#define CP_BULK(dst, src, bytes, mbar) \
    asm volatile("cp.async.bulk.shared::cta.global.mbarrier::complete_tx::bytes [%0], [%1], %2, [%3];" \
        :: "r"(dst), "l"(src), "r"(bytes), "r"(mbar) : "memory")

// swizzled byte offset inside a row: granule16 g -> g ^ (row&7)
__device__ __forceinline__ uint32_t swz(int row, int kb, int rowbytes) {
    uint32_t g = (uint32_t)(kb >> 4);
    return (uint32_t)row * rowbytes + (((g ^ (row & 7))) << 4) + (kb & 15);
}

// =======================================================================
// Kernel P: weight prep (fp16 for fused GEMMs, bf16 hi/lo for table GEMM)
// =======================================================================
#define PREP_ITEMS  (256*64 + 16*256 + 256*384)
#define PREP_BLOCKS ((PREP_ITEMS + 255) / 256)

__global__ void prep_kernel(const float* __restrict__ W1,
                            const float* __restrict__ W2) {
    int i = blockIdx.x * blockDim.x + threadIdx.x;
    if (i < 256 * 64) {
        int n = i >> 6, k = i & 63;
        float w = W1[(size_t)k * KHID + n];
        *(__half*)(g_B1 + swz(n, 2 * k, 128)) = __float2half_rn(w);
    } else if (i < 256 * 64 + 16 * 256) {
        int ii = i - 256 * 64;
        int o = ii >> 8, k = ii & 255;
        float w = W2[(size_t)k * KOUT + o];
        *(__half*)(g_B2 + swz(o, 2 * k, 512)) = __float2half_rn(w);
    } else if (i < PREP_ITEMS) {
        int ii = i - (256 * 64 + 16 * 256);
        int n = ii / 384, k = ii % 384;
        float w = W1[(size_t)(KPF + k) * KHID + n];
        __nv_bfloat16 hi = __float2bfloat16_rn(w);
        __nv_bfloat16 lo = __float2bfloat16_rn(w - __bfloat162float(hi));
        int c = k >> 6, kl = k & 63;
        unsigned char* base = g_TB + (size_t)(c * 2) * 32768;
        *(__nv_bfloat16*)(base + swz(n, 2 * kl, 128)) = hi;
        *(__nv_bfloat16*)(base + 32768 + swz(n, 2 * kl, 128)) = lo;
    }
}

// =======================================================================
// Kernel B: FUSED mean + table GEMM. grid (43), 256 thr, N=256 per block.
//   A-staging computes the 6-view mean from patch_tokens directly
//   (fp32 sum, identical arithmetic to the old mean kernel), splits to
//   bf16 hi/lo in 6 k64-chunk planes. B (hi+lo) streamed per chunk.
// SMEM: A 6x16KB @0 (96KB), B 64KB @98304 (hi 32K | lo 32K), mbar @163840
// =======================================================================
#define TOFF_B 98304u
#define TOFF_MBAR 163840u
#define TSMEM_BYTES 163968u

__global__ void __launch_bounds__(256, 1)
table_mma_kernel(const float* __restrict__ pt, const float* __restrict__ b1) {
    extern __shared__ char smc[];
    const uint32_t sb = smem_u32(smc);
    const int t = threadIdx.x;
    const int l = t & 31;
    const int wid = t >> 5;
    const int m0 = blockIdx.x * 64;

    if (t == 0) MBAR_INIT(sb + TOFF_MBAR, 1);
    __syncthreads();
    if (t == 0) {
        MBAR_EXPECT(sb + TOFF_MBAR, 65536u);
        CP_BULK(sb + TOFF_B, (const void*)g_TB, 32768u, sb + TOFF_MBAR);
        CP_BULK(sb + TOFF_B + 32768u, (const void*)(g_TB + 32768), 32768u, sb + TOFF_MBAR);
    }

    // ---- stage A: mean over 6 views from pt, bf16 hi/lo split ----
    {
        const float4* base = (const float4*)pt;
        const float inv = 1.0f / KNV;
#pragma unroll
        for (int it = 0; it < 24; it++) {
            int idx = t + it * 256;          // 0..6143 float4s
            int r = idx / 96;
            int q = idx - r * 96;            // float4 within row
            int col = 4 * q;
            int rg = m0 + r;
            float4 s = make_float4(0.f, 0.f, 0.f, 0.f);
            if (rg < ROWS_T) {
                int b = (rg >= KM) ? 1 : 0;
                int m = rg - b * KM;
#pragma unroll
                for (int vw = 0; vw < KNV; vw++) {
                    float4 x = base[((size_t)(b * KNV + vw) * KM + m) * (KDIM / 4) + q];
                    s.x += x.x; s.y += x.y; s.z += x.z; s.w += x.w;
                }
                s.x *= inv; s.y *= inv; s.z *= inv; s.w *= inv;
            }
            __nv_bfloat162 h0 = __floats2bfloat162_rn(s.x, s.y);
            __nv_bfloat162 h1 = __floats2bfloat162_rn(s.z, s.w);
            __nv_bfloat162 l0 = __floats2bfloat162_rn(s.x - __low2float(h0), s.y - __high2float(h0));
            __nv_bfloat162 l1 = __floats2bfloat162_rn(s.z - __low2float(h1), s.w - __high2float(h1));
            uint2 hp, lp;
            memcpy(&hp.x, &h0, 4); memcpy(&hp.y, &h1, 4);
            memcpy(&lp.x, &l0, 4); memcpy(&lp.y, &l1, 4);
            int c = col >> 6, kl = col & 63;
            *(uint2*)(smc + c * 16384 + swz(r, 2 * kl, 256)) = hp;
            *(uint2*)(smc + c * 16384 + swz(r, 128 + 2 * kl, 256)) = lp;
        }
    }
    __syncthreads();

    // warp mapping: 2 m-slices of 32, 4 n-slices of 64
    const int wm = wid & 1, wn = wid >> 1;
    const int mrow = wm * 32, ncl = wn * 64;
    const int aRow = (l & 7) + ((l >> 3) & 1) * 8;
    const int aG   = l >> 4;
    const int bRow = ((l >> 4) << 3) + (l & 7);
    const int bG   = (l >> 3) & 1;

    float acc[2][8][4];
#pragma unroll
    for (int a = 0; a < 2; a++)
#pragma unroll
        for (int b_ = 0; b_ < 8; b_++)
#pragma unroll
            for (int q = 0; q < 4; q++) acc[a][b_][q] = 0.f;

    for (int c = 0; c < 6; c++) {
        MBAR_WAIT(sb + TOFF_MBAR, c & 1);
        const uint32_t abase = sb + (uint32_t)c * 16384u;
#pragma unroll
        for (int ks = 0; ks < 4; ks++) {
            const int kbh = ks * 32;
            uint32_t ah[2][4], al[2][4];
#pragma unroll
            for (int mt = 0; mt < 2; mt++) {
                int row = mrow + mt * 16 + aRow;
                ldsm4(abase + (uint32_t)row * 256u + ((((kbh >> 4) + aG) ^ (row & 7)) << 4), ah[mt]);
                ldsm4(abase + (uint32_t)row * 256u + (((((128 + kbh) >> 4) + aG) ^ (row & 7)) << 4), al[mt]);
            }
#pragma unroll
            for (int np = 0; np < 4; np++) {
                int row = ncl + np * 16 + bRow;
                uint32_t bh[4], bl[4];
                ldsm4(sb + TOFF_B + (uint32_t)row * 128u + ((((kbh >> 4) + bG) ^ (row & 7)) << 4), bh);
                ldsm4(sb + TOFF_B + 32768u + (uint32_t)row * 128u + ((((kbh >> 4) + bG) ^ (row & 7)) << 4), bl);
#pragma unroll
                for (int mt = 0; mt < 2; mt++) {
                    mma16816(acc[mt][np * 2 + 0], ah[mt], bh);
                    mma16816(acc[mt][np * 2 + 1], ah[mt], bh + 2);
                }
#pragma unroll
                for (int mt = 0; mt < 2; mt++) {
                    mma16816(acc[mt][np * 2 + 0], al[mt], bh);
                    mma16816(acc[mt][np * 2 + 1], al[mt], bh + 2);
                }
#pragma unroll
                for (int mt = 0; mt < 2; mt++) {
                    mma16816(acc[mt][np * 2 + 0], ah[mt], bl);
                    mma16816(acc[mt][np * 2 + 1], ah[mt], bl + 2);
                }
            }
        }
        __syncthreads();
        if (c < 5 && t == 0) {
            MBAR_EXPECT(sb + TOFF_MBAR, 65536u);
            CP_BULK(sb + TOFF_B, (const void*)(g_TB + (size_t)(c + 1) * 65536), 32768u, sb + TOFF_MBAR);
            CP_BULK(sb + TOFF_B + 32768u, (const void*)(g_TB + (size_t)(c + 1) * 65536 + 32768), 32768u, sb + TOFF_MBAR);
        }
    }

    // ---- epilogue: + b1, store fp16 table ----
    {
        const int rb = l >> 2, cq = (l & 3) * 2;
#pragma unroll
        for (int mt = 0; mt < 2; mt++) {
            int r0 = m0 + mrow + mt * 16 + rb;
            int r1 = r0 + 8;
#pragma unroll
            for (int nt = 0; nt < 8; nt++) {
                int col = ncl + nt * 8 + cq;
                float2 bb = *(const float2*)&b1[col];
                if (r0 < ROWS_T)
                    *(__half2*)&g_T16[(size_t)r0 * KHID + col] =
                        __float22half2_rn(make_float2(acc[mt][nt][0] + bb.x, acc[mt][nt][1] + bb.y));
                if (r1 < ROWS_T)
                    *(__half2*)&g_T16[(size_t)r1 * KHID + col] =
                        __float22half2_rn(make_float2(acc[mt][nt][2] + bb.x, acc[mt][nt][3] + bb.y));
            }
        }
    }
}

// =======================================================================
// Kernel C: fused plain-fp16 mma kernel. 64 voxels / block, 8 warps.
//   (unchanged from R14: plain fp16 GEMM1+GEMM2, reg-prefetched gather)
// SMEM: A1 8K @0, B1 32K @8192, B2 8K @40960, sIdx @49152, mbar @49408
// =======================================================================
#define OFF_A1   0u
#define OFF_B1   8192u
#define OFF_B2   40960u
#define OFF_SIDX 49152u
#define OFF_MBAR 49408u
#define SMEMC_BYTES 49536u
#define VB 64
#define PSTRIDE 20

__global__ void __launch_bounds__(256, 2)
fused_kernel(const float* __restrict__ vf, const float* __restrict__ vc,
             const float* __restrict__ Km, const float* __restrict__ Rt,
             const float* __restrict__ b2, float* __restrict__ out) {
    extern __shared__ char smc[];
    const uint32_t sb = smem_u32(smc);
    const int t = threadIdx.x;
    const int l = t & 31;
    const int wid = t >> 5;
    const int g0 = blockIdx.x * VB;
    int* sIdx = (int*)(smc + OFF_SIDX);

    if (t == 0) {
        MBAR_INIT(sb + OFF_MBAR, 1);
        MBAR_EXPECT(sb + OFF_MBAR, 40960u);
        CP_BULK(sb + OFF_B1, (const void*)g_B1, 32768u, sb + OFF_MBAR);
        CP_BULK(sb + OFF_B2, (const void*)g_B2, 8192u, sb + OFF_MBAR);
    }

    // ---- stage A1: vf[64][64] fp32 -> fp16, rowbytes 128 ----
    {
        const float4* vsrc = (const float4*)(vf + (size_t)g0 * KPF);
#pragma unroll
        for (int it = 0; it < 4; it++) {
            int idx = t + it * 256;
            int r  = idx >> 4;
            int k4 = idx & 15;
            float4 x = vsrc[idx];
            __half2 h0 = __float22half2_rn(make_float2(x.x, x.y));
            __half2 h1 = __float22half2_rn(make_float2(x.z, x.w));
            uint2 hp;
            memcpy(&hp.x, &h0, 4); memcpy(&hp.y, &h1, 4);
            *(uint2*)(smc + OFF_A1 + swz(r, 8 * k4, 128)) = hp;
        }
    }
    // ---- projection -> token row index ----
    if (t < VB) {
        int g = g0 + t;
        int b = g >> 16;
        const float* c = vc + (size_t)g * 3;
        float x = c[0], y = c[1], z = c[2];
        float cam0 = Rt[0] * x + Rt[1] * y + Rt[2]  * z + Rt[3];
        float cam1 = Rt[4] * x + Rt[5] * y + Rt[6]  * z + Rt[7];
        float cam2 = Rt[8] * x + Rt[9] * y + Rt[10] * z + Rt[11];
        float p0 = Km[0] * cam0 + Km[1] * cam1 + Km[2] * cam2;
        float p1 = Km[3] * cam0 + Km[4] * cam1 + Km[5] * cam2;
        float p2 = Km[6] * cam0 + Km[7] * cam1 + Km[8] * cam2;
        float denom = p2 + 1e-6f;
        float u  = __fdiv_rn(p0, denom) * (float)(518.0 / 600.0);
        float vv = __fdiv_rn(p1, denom) * (float)(518.0 / 900.0);
        int px = (int)__fdiv_rn(u, 14.0f);
        int py = (int)__fdiv_rn(vv, 14.0f);
        px = min(max(px, 0), KGRID - 1);
        py = min(max(py, 0), KGRID - 1);
        sIdx[t] = b * KM + px * KGRID + py;
    }
    __syncthreads();

    const int wm = wid & 1, wn = wid >> 1;
    const int mrow = wm * 32, ncol = wn * 64;
    const int aRow = (l & 7) + ((l >> 3) & 1) * 8;
    const int aG   = l >> 4;
    const int bRow = ((l >> 4) << 3) + (l & 7);
    const int bG   = (l >> 3) & 1;
    const int rb = l >> 2, cq = (l & 3) * 2;

    // ---- register prefetch of gathered T (hidden by GEMM1) ----
    uint32_t tpre0[2][8], tpre1[2][8];
#pragma unroll
    for (int mt = 0; mt < 2; mt++) {
        int r0 = mrow + mt * 16 + rb;
        const __half* T0 = g_T16 + (size_t)sIdx[r0] * KHID;
        const __half* T1 = g_T16 + (size_t)sIdx[r0 + 8] * KHID;
#pragma unroll
        for (int nt = 0; nt < 8; nt++) {
            int c0 = ncol + nt * 8 + cq;
            tpre0[mt][nt] = *(const uint32_t*)(T0 + c0);
            tpre1[mt][nt] = *(const uint32_t*)(T1 + c0);
        }
    }

    MBAR_WAIT(sb + OFF_MBAR, 0);

    // ---- GEMM1: warp tile 32m x 64n; 4 k-steps, plain fp16 ----
    float acc[2][8][4];
#pragma unroll
    for (int a = 0; a < 2; a++)
#pragma unroll
        for (int b_ = 0; b_ < 8; b_++)
#pragma unroll
            for (int q = 0; q < 4; q++) acc[a][b_][q] = 0.f;

#pragma unroll
    for (int ks = 0; ks < 4; ks++) {
        const int kb = ks * 32;
        uint32_t ahf[2][4];
#pragma unroll
        for (int mt = 0; mt < 2; mt++) {
            int row = mrow + mt * 16 + aRow;
            ldsm4(sb + OFF_A1 + (uint32_t)row * 128u + ((((kb >> 4) + aG) ^ (row & 7)) << 4), ahf[mt]);
        }
#pragma unroll
        for (int npp = 0; npp < 2; npp++) {
            int row0 = ncol + (npp * 2 + 0) * 16 + bRow;
            int row1 = ncol + (npp * 2 + 1) * 16 + bRow;
            uint32_t bh0[4], bh1[4];
            ldsm4(sb + OFF_B1 + (uint32_t)row0 * 128u + ((((kb >> 4) + bG) ^ (row0 & 7)) << 4), bh0);
            ldsm4(sb + OFF_B1 + (uint32_t)row1 * 128u + ((((kb >> 4) + bG) ^ (row1 & 7)) << 4), bh1);
            mma16816h(acc[0][npp * 4 + 0], ahf[0], bh0);  mma16816h(acc[0][npp * 4 + 1], ahf[0], bh0 + 2);
            mma16816h(acc[1][npp * 4 + 0], ahf[1], bh0);  mma16816h(acc[1][npp * 4 + 1], ahf[1], bh0 + 2);
            mma16816h(acc[0][npp * 4 + 2], ahf[0], bh1);  mma16816h(acc[0][npp * 4 + 3], ahf[0], bh1 + 2);
            mma16816h(acc[1][npp * 4 + 2], ahf[1], bh1);  mma16816h(acc[1][npp * 4 + 3], ahf[1], bh1 + 2);
        }
    }

    // ---- epilogue IN REGISTERS: + prefetched T, relu, fp16 pack ----
    uint32_t ah[2][4][4];
    {
#pragma unroll
        for (int mt = 0; mt < 2; mt++) {
#pragma unroll
            for (int nt = 0; nt < 8; nt++) {
                __half2 t0h, t1h;
                memcpy(&t0h, &tpre0[mt][nt], 4);
                memcpy(&t1h, &tpre1[mt][nt], 4);
                float2 t0 = __half22float2(t0h);
                float2 t1 = __half22float2(t1h);
                float h00 = fmaxf(acc[mt][nt][0] + t0.x, 0.f);
                float h01 = fmaxf(acc[mt][nt][1] + t0.y, 0.f);
                float h10 = fmaxf(acc[mt][nt][2] + t1.x, 0.f);
                float h11 = fmaxf(acc[mt][nt][3] + t1.y, 0.f);
                __half2 hA = __float22half2_rn(make_float2(h00, h01));
                __half2 hB = __float22half2_rn(make_float2(h10, h11));
                int kb = nt >> 1, hf = (nt & 1) * 2;
                memcpy(&ah[mt][kb][hf + 0], &hA, 4);
                memcpy(&ah[mt][kb][hf + 1], &hB, 4);
            }
        }
    }

    // ---- GEMM2: per-warp partial over k-slice [ncol, ncol+64), plain ----
    float d[2][2][4];
#pragma unroll
    for (int mt = 0; mt < 2; mt++)
#pragma unroll
        for (int j = 0; j < 2; j++)
#pragma unroll
            for (int q = 0; q < 4; q++) d[mt][j][q] = 0.f;

#pragma unroll
    for (int kb = 0; kb < 4; kb++) {
        int ghi = (ncol >> 3) + 2 * kb + bG;
        uint32_t bhf[4];
        ldsm4(sb + OFF_B2 + (uint32_t)bRow * 512u + (((uint32_t)(ghi ^ (bRow & 7))) << 4), bhf);
        mma16816h(d[0][0], ah[0][kb], bhf);     mma16816h(d[0][1], ah[0][kb], bhf + 2);
        mma16816h(d[1][0], ah[1][kb], bhf);     mma16816h(d[1][1], ah[1][kb], bhf + 2);
    }

    __syncthreads();   // A1/B1 region dead -> reuse as P

    // ---- store partials P[wn][64][PSTRIDE] and reduce over wn ----
    {
        float* P = (float*)smc;
        const int c2 = (l & 3) * 2;
#pragma unroll
        for (int mt = 0; mt < 2; mt++) {
            int r0 = mrow + mt * 16 + rb;
#pragma unroll
            for (int j = 0; j < 2; j++) {
                int cc = j * 8 + c2;
                *(float2*)&P[(wn * 64 + r0) * PSTRIDE + cc] = make_float2(d[mt][j][0], d[mt][j][1]);
                *(float2*)&P[(wn * 64 + r0 + 8) * PSTRIDE + cc] = make_float2(d[mt][j][2], d[mt][j][3]);
            }
        }
    }
    __syncthreads();
    {
        const float* P = (const float*)smc;
        int row = t >> 2;
        int cq4 = (t & 3) * 4;
        float4 s0 = *(const float4*)&P[(0 * 64 + row) * PSTRIDE + cq4];
        float4 s1 = *(const float4*)&P[(1 * 64 + row) * PSTRIDE + cq4];
        float4 s2 = *(const float4*)&P[(2 * 64 + row) * PSTRIDE + cq4];
        float4 s3 = *(const float4*)&P[(3 * 64 + row) * PSTRIDE + cq4];
        float4 bv = *(const float4*)(b2 + cq4);
        float4 o;
        o.x = s0.x + s1.x + s2.x + s3.x + bv.x;
        o.y = s0.y + s1.y + s2.y + s3.y + bv.y;
        o.z = s0.z + s1.z + s2.z + s3.z + bv.z;
        o.w = s0.w + s1.w + s2.w + s3.w + bv.w;
        *(float4*)(out + (size_t)(g0 + row) * KOUT + cq4) = o;
    }
}

// =======================================================================
extern "C" void kernel_launch(void* const* d_in, const int* in_sizes, int n_in,
                              void* d_out, int out_size) {
    (void)in_sizes; (void)n_in; (void)out_size;
    const float* pt = (const float*)d_in[0];
    const float* vf = (const float*)d_in[1];
    const float* vc = (const float*)d_in[2];
    const float* Km = (const float*)d_in[3];
    const float* Rt = (const float*)d_in[4];
    const float* W1 = (const float*)d_in[5];
    const float* b1 = (const float*)d_in[6];
    const float* W2 = (const float*)d_in[7];
    const float* b2 = (const float*)d_in[8];
    float* out = (float*)d_out;

    prep_kernel<<<PREP_BLOCKS, 256>>>(W1, W2);

    cudaFuncSetAttribute(table_mma_kernel,
                         cudaFuncAttributeMaxDynamicSharedMemorySize,
                         TSMEM_BYTES);
    table_mma_kernel<<<ROWS_PAD / 64, 256, TSMEM_BYTES>>>(pt, b1);

    cudaFuncSetAttribute(fused_kernel,
                         cudaFuncAttributeMaxDynamicSharedMemorySize,
                         SMEMC_BYTES);
    fused_kernel<<<KGV / VB, 256, SMEMC_BYTES>>>(vf, vc, Km, Rt, b2, out);
}

// round 16
// speedup vs baseline: 1.2214x; 1.2214x over previous
#include <cuda_runtime.h>
#include <cuda_bf16.h>
#include <cuda_fp16.h>
#include <cstdint>
#include <string.h>

// ---------------- problem constants ----------------
#define KB    2
#define KNV   6
#define KM    1369
#define KDIM  384
#define KV    65536
#define KPF   64
#define KHID  256
#define KOUT  16
#define KGRID 37
#define KGV   (KB*KV)
#define ROWS_T (KB*KM)        // 2738
#define ROWS_PAD 2752         // 43*64

// ---------------- device scratch ----------------
__device__ float g_mean[KB*KM*KDIM];
__device__ __half g_T16[ROWS_T*KHID];      // token table fp16 (incl b1)
__device__ unsigned char g_B1[32768];      // W1top^T fp16, swizzled [256r][128B]
__device__ unsigned char g_B2[8192];       // W2^T    fp16, swizzled [16r][512B]
// W1bot^T bf16, 6 chunks of k64: chunk c: hi plane [256r][128B] then lo plane
__device__ unsigned char g_TB[6*2*32768];

// ---------------- helpers ----------------
__device__ __forceinline__ uint32_t smem_u32(const void* p) {
    uint32_t a;
    asm("{ .reg .u64 t; cvta.to.shared.u64 t, %1; cvt.u32.u64 %0, t; }" : "=r"(a) : "l"(p));
    return a;
}
__device__ __forceinline__ void ldsm4(uint32_t a, uint32_t* r) {
    asm volatile("ldmatrix.sync.aligned.m8n8.x4.shared.b16 {%0,%1,%2,%3}, [%4];"
        : "=r"(r[0]), "=r"(r[1]), "=r"(r[2]), "=r"(r[3]) : "r"(a));
}
// bf16 mma (table kernel)
__device__ __forceinline__ void mma16816(float* c, const uint32_t* a, const uint32_t* b) {
    asm volatile("mma.sync.aligned.m16n8k16.row.col.f32.bf16.bf16.f32 "
        "{%0,%1,%2,%3}, {%4,%5,%6,%7}, {%8,%9}, {%0,%1,%2,%3};"
        : "+f"(c[0]), "+f"(c[1]), "+f"(c[2]), "+f"(c[3])
        : "r"(a[0]), "r"(a[1]), "r"(a[2]), "r"(a[3]), "r"(b[0]), "r"(b[1]));
}
// fp16 mma (fused kernel)
__device__ __forceinline__ void mma16816h(float* c, const uint32_t* a, const uint32_t* b) {
    asm volatile("mma.sync.aligned.m16n8k16.row.col.f32.f16.f16.f32 "
        "{%0,%1,%2,%3}, {%4,%5,%6,%7}, {%8,%9}, {%0,%1,%2,%3};"
        : "+f"(c[0]), "+f"(c[1]), "+f"(c[2]), "+f"(c[3])
        : "r"(a[0]), "r"(a[1]), "r"(a[2]), "r"(a[3]), "r"(b[0]), "r"(b[1]));
}
#define MBAR_INIT(a, n) asm volatile("mbarrier.init.shared.b64 [%0], %1;" :: "r"(a), "r"(n) : "memory")
#define MBAR_EXPECT(a, b) asm volatile("mbarrier.arrive.expect_tx.shared.b64 _, [%0], %1;" :: "r"(a), "r"(b) : "memory")
#define MBAR_WAIT(a, ph) do { \
    uint32_t _m = (a), _p = (ph), _d; \
    asm volatile("{ .reg .pred p; mbarrier.try_wait.parity.shared.b64 p, [%1], %2; selp.b32 %0,1,0,p; }" \
        : "=r"(_d) : "r"(_m), "r"(_p) : "memory"); \
    if (!_d) { \
        asm volatile("{ .reg .pred P1;\nWL_%=:\n mbarrier.try_wait.parity.shared.b64 P1, [%0], %1;\n @P1 bra.uni WD_%=;\n bra.uni WL_%=;\nWD_%=:\n}" \
            :: "r"(_m), "r"(_p) : "memory"); \
    } } while (0)
#define CP_BULK(dst, src, bytes, mbar) \
    asm volatile("cp.async.bulk.shared::cta.global.mbarrier::complete_tx::bytes [%0], [%1], %2, [%3];" \
        :: "r"(dst), "l"(src), "r"(bytes), "r"(mbar) : "memory")

// swizzled byte offset inside a row: granule16 g -> g ^ (row&7)
__device__ __forceinline__ uint32_t swz(int row, int kb, int rowbytes) {
    uint32_t g = (uint32_t)(kb >> 4);
    return (uint32_t)row * rowbytes + (((g ^ (row & 7))) << 4) + (kb & 15);
}

// =======================================================================
// Kernel A+P merged: mean over views (split-halves ILP, coalesced) + prep
// =======================================================================
#define MEAN_TOTAL4 (KB*KM*KDIM/4)                   // 262848
#define MEAN_HALF   (MEAN_TOTAL4 / 2)                // 131424
#define MEAN_BLOCKS ((MEAN_HALF + 255) / 256)        // 514
#define PREP_ITEMS  (256*64 + 16*256 + 256*384)
#define PREP_BLOCKS ((PREP_ITEMS + 255) / 256)

__global__ void mean_prep_kernel(const float* __restrict__ pt,
                                 const float* __restrict__ W1,
                                 const float* __restrict__ W2) {
    if (blockIdx.x < MEAN_BLOCKS) {
        int p = blockIdx.x * blockDim.x + threadIdx.x;
        if (p >= MEAN_HALF) return;
        const float4* base = (const float4*)pt;
        const float inv = 1.0f / KNV;
        // two far-apart elements: coalescing preserved, MLP doubled
#pragma unroll
        for (int h = 0; h < 2; h++) {
            int i = p + h * MEAN_HALF;
            const int dq = i % (KDIM / 4);
            const int bm = i / (KDIM / 4);
            const int b = bm / KM;
            const int m = bm % KM;
            float4 s = make_float4(0.f, 0.f, 0.f, 0.f);
#pragma unroll
            for (int vw = 0; vw < KNV; vw++) {
                float4 x = base[((size_t)(b * KNV + vw) * KM + m) * (KDIM / 4) + dq];
                s.x += x.x; s.y += x.y; s.z += x.z; s.w += x.w;
            }
            s.x *= inv; s.y *= inv; s.z *= inv; s.w *= inv;
            ((float4*)g_mean)[i] = s;
        }
    } else {
        int i = (blockIdx.x - MEAN_BLOCKS) * blockDim.x + threadIdx.x;
        if (i < 256 * 64) {
            int n = i >> 6, k = i & 63;
            float w = W1[(size_t)k * KHID + n];
            *(__half*)(g_B1 + swz(n, 2 * k, 128)) = __float2half_rn(w);
        } else if (i < 256 * 64 + 16 * 256) {
            int ii = i - 256 * 64;
            int o = ii >> 8, k = ii & 255;
            float w = W2[(size_t)k * KOUT + o];
            *(__half*)(g_B2 + swz(o, 2 * k, 512)) = __float2half_rn(w);
        } else if (i < PREP_ITEMS) {
            int ii = i - (256 * 64 + 16 * 256);
            int n = ii / 384, k = ii % 384;
            float w = W1[(size_t)(KPF + k) * KHID + n];
            __nv_bfloat16 hi = __float2bfloat16_rn(w);
            __nv_bfloat16 lo = __float2bfloat16_rn(w - __bfloat162float(hi));
            int c = k >> 6, kl = k & 63;
            unsigned char* base = g_TB + (size_t)(c * 2) * 32768;
            *(__nv_bfloat16*)(base + swz(n, 2 * kl, 128)) = hi;
            *(__nv_bfloat16*)(base + 32768 + swz(n, 2 * kl, 128)) = lo;
        }
    }
}

// =======================================================================
// Kernel B: table GEMM via bf16 3-term mma -> fp16 table. grid (43, 2).
// =======================================================================
#define TOFF_B 98304u
#define TOFF_MBAR 131072u
#define TSMEM_BYTES 131200u

__global__ void __launch_bounds__(256, 1)
table_mma_kernel(const float* __restrict__ b1) {
    extern __shared__ char smc[];
    const uint32_t sb = smem_u32(smc);
    const int t = threadIdx.x;
    const int l = t & 31;
    const int wid = t >> 5;
    const int m0 = blockIdx.x * 64;
    const int ny = blockIdx.y;

    if (t == 0) MBAR_INIT(sb + TOFF_MBAR, 1);
    __syncthreads();
    if (t == 0) {
        MBAR_EXPECT(sb + TOFF_MBAR, 32768u);
        CP_BULK(sb + TOFF_B, (const void*)(g_TB + (size_t)ny * 16384), 16384u, sb + TOFF_MBAR);
        CP_BULK(sb + TOFF_B + 16384u, (const void*)(g_TB + 32768 + (size_t)ny * 16384), 16384u, sb + TOFF_MBAR);
    }

#pragma unroll
    for (int it = 0; it < 24; it++) {
        int idx = t + it * 256;
        int r = idx / 96;
        int q = idx - r * 96;
        int col = 4 * q;
        float4 x = make_float4(0.f, 0.f, 0.f, 0.f);
        if (m0 + r < ROWS_T)
            x = *(const float4*)&g_mean[(size_t)(m0 + r) * KDIM + col];
        __nv_bfloat162 h0 = __floats2bfloat162_rn(x.x, x.y);
        __nv_bfloat162 h1 = __floats2bfloat162_rn(x.z, x.w);
        __nv_bfloat162 l0 = __floats2bfloat162_rn(x.x - __low2float(h0), x.y - __high2float(h0));
        __nv_bfloat162 l1 = __floats2bfloat162_rn(x.z - __low2float(h1), x.w - __high2float(h1));
        uint2 hp, lp;
        memcpy(&hp.x, &h0, 4); memcpy(&hp.y, &h1, 4);
        memcpy(&lp.x, &l0, 4); memcpy(&lp.y, &l1, 4);
        int c = col >> 6, kl = col & 63;
        *(uint2*)(smc + c * 16384 + swz(r, 2 * kl, 256)) = hp;
        *(uint2*)(smc + c * 16384 + swz(r, 128 + 2 * kl, 256)) = lp;
    }
    __syncthreads();

    const int wm = wid & 1, wn = wid >> 1;
    const int mrow = wm * 32, ncl = wn * 32;
    const int aRow = (l & 7) + ((l >> 3) & 1) * 8;
    const int aG   = l >> 4;
    const int bRow = ((l >> 4) << 3) + (l & 7);
    const int bG   = (l >> 3) & 1;

    float acc[2][4][4];
#pragma unroll
    for (int a = 0; a < 2; a++)
#pragma unroll
        for (int b_ = 0; b_ < 4; b_++)
#pragma unroll
            for (int q = 0; q < 4; q++) acc[a][b_][q] = 0.f;

    for (int c = 0; c < 6; c++) {
        MBAR_WAIT(sb + TOFF_MBAR, c & 1);
        const uint32_t abase = sb + (uint32_t)c * 16384u;
#pragma unroll
        for (int ks = 0; ks < 4; ks++) {
            const int kbh = ks * 32;
            uint32_t ah[2][4], al[2][4];
#pragma unroll
            for (int mt = 0; mt < 2; mt++) {
                int row = mrow + mt * 16 + aRow;
                ldsm4(abase + (uint32_t)row * 256u + ((((kbh >> 4) + aG) ^ (row & 7)) << 4), ah[mt]);
                ldsm4(abase + (uint32_t)row * 256u + (((((128 + kbh) >> 4) + aG) ^ (row & 7)) << 4), al[mt]);
            }
#pragma unroll
            for (int np = 0; np < 2; np++) {
                int row = ncl + np * 16 + bRow;
                uint32_t bh[4], bl[4];
                ldsm4(sb + TOFF_B + (uint32_t)row * 128u + ((((kbh >> 4) + bG) ^ (row & 7)) << 4), bh);
                ldsm4(sb + TOFF_B + 16384u + (uint32_t)row * 128u + ((((kbh >> 4) + bG) ^ (row & 7)) << 4), bl);
#pragma unroll
                for (int mt = 0; mt < 2; mt++) {
                    mma16816(acc[mt][np * 2 + 0], ah[mt], bh);
                    mma16816(acc[mt][np * 2 + 1], ah[mt], bh + 2);
                }
#pragma unroll
                for (int mt = 0; mt < 2; mt++) {
                    mma16816(acc[mt][np * 2 + 0], al[mt], bh);
                    mma16816(acc[mt][np * 2 + 1], al[mt], bh + 2);
                }
#pragma unroll
                for (int mt = 0; mt < 2; mt++) {
                    mma16816(acc[mt][np * 2 + 0], ah[mt], bl);
                    mma16816(acc[mt][np * 2 + 1], ah[mt], bl + 2);
                }
            }
        }
        __syncthreads();
        if (c < 5 && t == 0) {
            MBAR_EXPECT(sb + TOFF_MBAR, 32768u);
            CP_BULK(sb + TOFF_B, (const void*)(g_TB + (size_t)(c + 1) * 65536 + (size_t)ny * 16384), 16384u, sb + TOFF_MBAR);
            CP_BULK(sb + TOFF_B + 16384u, (const void*)(g_TB + (size_t)(c + 1) * 65536 + 32768 + (size_t)ny * 16384), 16384u, sb + TOFF_MBAR);
        }
    }

    {
        const int rb = l >> 2, cq = (l & 3) * 2;
#pragma unroll
        for (int mt = 0; mt < 2; mt++) {
            int r0 = m0 + mrow + mt * 16 + rb;
            int r1 = r0 + 8;
#pragma unroll
            for (int nt = 0; nt < 4; nt++) {
                int col = ny * 128 + ncl + nt * 8 + cq;
                float2 bb = *(const float2*)&b1[col];
                if (r0 < ROWS_T)
                    *(__half2*)&g_T16[(size_t)r0 * KHID + col] =
                        __float22half2_rn(make_float2(acc[mt][nt][0] + bb.x, acc[mt][nt][1] + bb.y));
                if (r1 < ROWS_T)
                    *(__half2*)&g_T16[(size_t)r1 * KHID + col] =
                        __float22half2_rn(make_float2(acc[mt][nt][2] + bb.x, acc[mt][nt][3] + bb.y));
            }
        }
    }
}

// =======================================================================
// Kernel C: fused plain-fp16 mma kernel. 64 voxels / block, 8 warps.
// SMEM: A1 8K @0, B1 32K @8192, B2 8K @40960, sIdx @49152, mbar @49408
// =======================================================================
#define OFF_A1   0u
#define OFF_B1   8192u
#define OFF_B2   40960u
#define OFF_SIDX 49152u
#define OFF_MBAR 49408u
#define SMEMC_BYTES 49536u
#define VB 64
#define PSTRIDE 20

__global__ void __launch_bounds__(256, 2)
fused_kernel(const float* __restrict__ vf, const float* __restrict__ vc,
             const float* __restrict__ Km, const float* __restrict__ Rt,
             const float* __restrict__ b2, float* __restrict__ out) {
    extern __shared__ char smc[];
    const uint32_t sb = smem_u32(smc);
    const int t = threadIdx.x;
    const int l = t & 31;
    const int wid = t >> 5;
    const int g0 = blockIdx.x * VB;
    int* sIdx = (int*)(smc + OFF_SIDX);

    if (t == 0) {
        MBAR_INIT(sb + OFF_MBAR, 1);
        MBAR_EXPECT(sb + OFF_MBAR, 40960u);
        CP_BULK(sb + OFF_B1, (const void*)g_B1, 32768u, sb + OFF_MBAR);
        CP_BULK(sb + OFF_B2, (const void*)g_B2, 8192u, sb + OFF_MBAR);
    }

    // ---- stage A1: vf[64][64] fp32 -> fp16, rowbytes 128 ----
    {
        const float4* vsrc = (const float4*)(vf + (size_t)g0 * KPF);
#pragma unroll
        for (int it = 0; it < 4; it++) {
            int idx = t + it * 256;
            int r  = idx >> 4;
            int k4 = idx & 15;
            float4 x = vsrc[idx];
            __half2 h0 = __float22half2_rn(make_float2(x.x, x.y));
            __half2 h1 = __float22half2_rn(make_float2(x.z, x.w));
            uint2 hp;
            memcpy(&hp.x, &h0, 4); memcpy(&hp.y, &h1, 4);
            *(uint2*)(smc + OFF_A1 + swz(r, 8 * k4, 128)) = hp;
        }
    }
    // ---- projection -> token row index ----
    if (t < VB) {
        int g = g0 + t;
        int b = g >> 16;
        const float* c = vc + (size_t)g * 3;
        float x = c[0], y = c[1], z = c[2];
        float cam0 = Rt[0] * x + Rt[1] * y + Rt[2]  * z + Rt[3];
        float cam1 = Rt[4] * x + Rt[5] * y + Rt[6]  * z + Rt[7];
        float cam2 = Rt[8] * x + Rt[9] * y + Rt[10] * z + Rt[11];
        float p0 = Km[0] * cam0 + Km[1] * cam1 + Km[2] * cam2;
        float p1 = Km[3] * cam0 + Km[4] * cam1 + Km[5] * cam2;
        float p2 = Km[6] * cam0 + Km[7] * cam1 + Km[8] * cam2;
        float denom = p2 + 1e-6f;
        float u  = __fdiv_rn(p0, denom) * (float)(518.0 / 600.0);
        float vv = __fdiv_rn(p1, denom) * (float)(518.0 / 900.0);
        int px = (int)__fdiv_rn(u, 14.0f);
        int py = (int)__fdiv_rn(vv, 14.0f);
        px = min(max(px, 0), KGRID - 1);
        py = min(max(py, 0), KGRID - 1);
        sIdx[t] = b * KM + px * KGRID + py;
    }
    __syncthreads();

    const int wm = wid & 1, wn = wid >> 1;
    const int mrow = wm * 32, ncol = wn * 64;
    const int aRow = (l & 7) + ((l >> 3) & 1) * 8;
    const int aG   = l >> 4;
    const int bRow = ((l >> 4) << 3) + (l & 7);
    const int bG   = (l >> 3) & 1;
    const int rb = l >> 2, cq = (l & 3) * 2;

    // ---- register prefetch of gathered T (hidden by GEMM1) ----
    uint32_t tpre0[2][8], tpre1[2][8];
#pragma unroll
    for (int mt = 0; mt < 2; mt++) {
        int r0 = mrow + mt * 16 + rb;
        const __half* T0 = g_T16 + (size_t)sIdx[r0] * KHID;
        const __half* T1 = g_T16 + (size_t)sIdx[r0 + 8] * KHID;
#pragma unroll
        for (int nt = 0; nt < 8; nt++) {
            int c0 = ncol + nt * 8 + cq;
            tpre0[mt][nt] = *(const uint32_t*)(T0 + c0);
            tpre1[mt][nt] = *(const uint32_t*)(T1 + c0);
        }
    }

    MBAR_WAIT(sb + OFF_MBAR, 0);

    // ---- GEMM1: warp tile 32m x 64n; 4 k-steps, plain fp16 ----
    float acc[2][8][4];
#pragma unroll
    for (int a = 0; a < 2; a++)
#pragma unroll
        for (int b_ = 0; b_ < 8; b_++)
#pragma unroll
            for (int q = 0; q < 4; q++) acc[a][b_][q] = 0.f;

#pragma unroll
    for (int ks = 0; ks < 4; ks++) {
        const int kb = ks * 32;
        uint32_t ahf[2][4];
#pragma unroll
        for (int mt = 0; mt < 2; mt++) {
            int row = mrow + mt * 16 + aRow;
            ldsm4(sb + OFF_A1 + (uint32_t)row * 128u + ((((kb >> 4) + aG) ^ (row & 7)) << 4), ahf[mt]);
        }
#pragma unroll
        for (int npp = 0; npp < 2; npp++) {
            int row0 = ncol + (npp * 2 + 0) * 16 + bRow;
            int row1 = ncol + (npp * 2 + 1) * 16 + bRow;
            uint32_t bh0[4], bh1[4];
            ldsm4(sb + OFF_B1 + (uint32_t)row0 * 128u + ((((kb >> 4) + bG) ^ (row0 & 7)) << 4), bh0);
            ldsm4(sb + OFF_B1 + (uint32_t)row1 * 128u + ((((kb >> 4) + bG) ^ (row1 & 7)) << 4), bh1);
            mma16816h(acc[0][npp * 4 + 0], ahf[0], bh0);  mma16816h(acc[0][npp * 4 + 1], ahf[0], bh0 + 2);
            mma16816h(acc[1][npp * 4 + 0], ahf[1], bh0);  mma16816h(acc[1][npp * 4 + 1], ahf[1], bh0 + 2);
            mma16816h(acc[0][npp * 4 + 2], ahf[0], bh1);  mma16816h(acc[0][npp * 4 + 3], ahf[0], bh1 + 2);
            mma16816h(acc[1][npp * 4 + 2], ahf[1], bh1);  mma16816h(acc[1][npp * 4 + 3], ahf[1], bh1 + 2);
        }
    }

    // ---- epilogue IN REGISTERS: + prefetched T, relu, fp16 pack ----
    uint32_t ah[2][4][4];
    {
#pragma unroll
        for (int mt = 0; mt < 2; mt++) {
#pragma unroll
            for (int nt = 0; nt < 8; nt++) {
                __half2 t0h, t1h;
                memcpy(&t0h, &tpre0[mt][nt], 4);
                memcpy(&t1h, &tpre1[mt][nt], 4);
                float2 t0 = __half22float2(t0h);
                float2 t1 = __half22float2(t1h);
                float h00 = fmaxf(acc[mt][nt][0] + t0.x, 0.f);
                float h01 = fmaxf(acc[mt][nt][1] + t0.y, 0.f);
                float h10 = fmaxf(acc[mt][nt][2] + t1.x, 0.f);
                float h11 = fmaxf(acc[mt][nt][3] + t1.y, 0.f);
                __half2 hA = __float22half2_rn(make_float2(h00, h01));
                __half2 hB = __float22half2_rn(make_float2(h10, h11));
                int kb = nt >> 1, hf = (nt & 1) * 2;
                memcpy(&ah[mt][kb][hf + 0], &hA, 4);
                memcpy(&ah[mt][kb][hf + 1], &hB, 4);
            }
        }
    }

    // ---- GEMM2: per-warp partial over k-slice [ncol, ncol+64), plain ----
    float d[2][2][4];
#pragma unroll
    for (int mt = 0; mt < 2; mt++)
#pragma unroll
        for (int j = 0; j < 2; j++)
#pragma unroll
            for (int q = 0; q < 4; q++) d[mt][j][q] = 0.f;

#pragma unroll
    for (int kb = 0; kb < 4; kb++) {
        int ghi = (ncol >> 3) + 2 * kb + bG;
        uint32_t bhf[4];
        ldsm4(sb + OFF_B2 + (uint32_t)bRow * 512u + (((uint32_t)(ghi ^ (bRow & 7))) << 4), bhf);
        mma16816h(d[0][0], ah[0][kb], bhf);     mma16816h(d[0][1], ah[0][kb], bhf + 2);
        mma16816h(d[1][0], ah[1][kb], bhf);     mma16816h(d[1][1], ah[1][kb], bhf + 2);
    }

    __syncthreads();   // A1/B1 region dead -> reuse as P

    // ---- store partials P[wn][64][PSTRIDE] and reduce over wn ----
    {
        float* P = (float*)smc;
        const int c2 = (l & 3) * 2;
#pragma unroll
        for (int mt = 0; mt < 2; mt++) {
            int r0 = mrow + mt * 16 + rb;
#pragma unroll
            for (int j = 0; j < 2; j++) {
                int cc = j * 8 + c2;
                *(float2*)&P[(wn * 64 + r0) * PSTRIDE + cc] = make_float2(d[mt][j][0], d[mt][j][1]);
                *(float2*)&P[(wn * 64 + r0 + 8) * PSTRIDE + cc] = make_float2(d[mt][j][2], d[mt][j][3]);
            }
        }
    }
    __syncthreads();
    {
        const float* P = (const float*)smc;
        int row = t >> 2;
        int cq4 = (t & 3) * 4;
        float4 s0 = *(const float4*)&P[(0 * 64 + row) * PSTRIDE + cq4];
        float4 s1 = *(const float4*)&P[(1 * 64 + row) * PSTRIDE + cq4];
        float4 s2 = *(const float4*)&P[(2 * 64 + row) * PSTRIDE + cq4];
        float4 s3 = *(const float4*)&P[(3 * 64 + row) * PSTRIDE + cq4];
        float4 bv = *(const float4*)(b2 + cq4);
        float4 o;
        o.x = s0.x + s1.x + s2.x + s3.x + bv.x;
        o.y = s0.y + s1.y + s2.y + s3.y + bv.y;
        o.z = s0.z + s1.z + s2.z + s3.z + bv.z;
        o.w = s0.w + s1.w + s2.w + s3.w + bv.w;
        *(float4*)(out + (size_t)(g0 + row) * KOUT + cq4) = o;
    }
}

// =======================================================================
extern "C" void kernel_launch(void* const* d_in, const int* in_sizes, int n_in,
                              void* d_out, int out_size) {
    (void)in_sizes; (void)n_in; (void)out_size;
    const float* pt = (const float*)d_in[0];
    const float* vf = (const float*)d_in[1];
    const float* vc = (const float*)d_in[2];
    const float* Km = (const float*)d_in[3];
    const float* Rt = (const float*)d_in[4];
    const float* W1 = (const float*)d_in[5];
    const float* b1 = (const float*)d_in[6];
    const float* W2 = (const float*)d_in[7];
    const float* b2 = (const float*)d_in[8];
    float* out = (float*)d_out;

    mean_prep_kernel<<<MEAN_BLOCKS + PREP_BLOCKS, 256>>>(pt, W1, W2);

    cudaFuncSetAttribute(table_mma_kernel,
                         cudaFuncAttributeMaxDynamicSharedMemorySize,
                         TSMEM_BYTES);
    dim3 gridT(ROWS_PAD / 64, 2);
    table_mma_kernel<<<gridT, 256, TSMEM_BYTES>>>(b1);

    cudaFuncSetAttribute(fused_kernel,
                         cudaFuncAttributeMaxDynamicSharedMemorySize,
                         SMEMC_BYTES);
    fused_kernel<<<KGV / VB, 256, SMEMC_BYTES>>>(vf, vc, Km, Rt, b2, out);
}